// round 6
// baseline (speedup 1.0000x reference)
#include <cuda_runtime.h>

#define BB 128
#define TT 1000
#define NN 1024
#define ALPHA_C 0.995f
#define VTH_C 2.0f

#define SCB 4                 // scan blocks
#define CPB (BB / SCB)        // chains per scan block = 32
#define CHUNK 50              // timesteps per chunk
#define NCHUNK (TT / CHUNK)   // 20
#define PAD (CHUNK + 1)       // conflict-free staging stride
#define GEMV_BLOCKS 588
#define TOTAL_BLOCKS (GEMV_BLOCKS + SCB)   // 592 = 4/SM * 148 SM
#define ROWS_PER_CHUNK (BB * CHUNK)        // 6400

// drive scratch, block-major: [SCB][TT][CPB]
__device__ float g_drive[SCB * TT * CPB];
// produced-count per (scan block, chunk); zero at load, re-zeroed by consumer
__device__ unsigned g_ctr[SCB * NCHUNK];

// ---------------------------------------------------------------------------
// sync / copy helpers
// ---------------------------------------------------------------------------
__device__ __forceinline__ void red_release_add(unsigned* p, unsigned v) {
    asm volatile("red.release.gpu.global.add.u32 [%0], %1;"
                 :: "l"(p), "r"(v) : "memory");
}
__device__ __forceinline__ unsigned ld_acquire(const unsigned* p) {
    unsigned v;
    asm volatile("ld.acquire.gpu.global.u32 %0, [%1];"
                 : "=r"(v) : "l"(p) : "memory");
    return v;
}
__device__ __forceinline__ void st_relaxed(unsigned* p, unsigned v) {
    asm volatile("st.relaxed.gpu.global.u32 [%0], %1;"
                 :: "l"(p), "r"(v) : "memory");
}
__device__ __forceinline__ void cp_async16(void* smem_dst, const void* gmem_src) {
    unsigned saddr = (unsigned)__cvta_generic_to_shared(smem_dst);
    asm volatile("cp.async.ca.shared.global [%0], [%1], 16;\n"
                 :: "r"(saddr), "l"(gmem_src) : "memory");
}
__device__ __forceinline__ void cp_async_commit() {
    asm volatile("cp.async.commit_group;\n" ::: "memory");
}
template <int N>
__device__ __forceinline__ void cp_async_wait() {
    asm volatile("cp.async.wait_group %0;\n" :: "n"(N) : "memory");
}

// ---------------------------------------------------------------------------
// producer: drive[b,t] = dot(x[b,t,:], w), warp per row.
// Work order: chunk-outer (for flow control), b-major within chunk,
// t contiguous within each 50-row strip (for DRAM/TLB locality).
// ---------------------------------------------------------------------------
__device__ void gemv_part(const float* __restrict__ x, const float* __restrict__ w) {
    const int lane  = threadIdx.x & 31;
    const int warp  = ((blockIdx.x - SCB) * blockDim.x + threadIdx.x) >> 5;
    const int nwarp = (GEMV_BLOCKS * 256) >> 5;

    const float4* __restrict__ w4 = (const float4*)w;
    float4 wr[8];
#pragma unroll
    for (int k = 0; k < 8; k++) wr[k] = w4[lane + 32 * k];

    const int R = BB * TT;
    for (int q = warp; q < R; q += nwarp) {
        const int chunk = q / ROWS_PER_CHUNK;          // 0..19
        const int rem   = q - chunk * ROWS_PER_CHUNK;  // 0..6399
        const int b     = rem / CHUNK;                 // 0..127
        const int t     = chunk * CHUNK + (rem - b * CHUNK);

        const float4* __restrict__ x4 = (const float4*)(x + ((size_t)b * TT + t) * NN);
        float s = 0.0f;
#pragma unroll
        for (int k = 0; k < 8; k++) {
            float4 xv = x4[lane + 32 * k];
            s += xv.x * wr[k].x;
            s += xv.y * wr[k].y;
            s += xv.z * wr[k].z;
            s += xv.w * wr[k].w;
        }
#pragma unroll
        for (int off = 16; off > 0; off >>= 1)
            s += __shfl_xor_sync(0xffffffffu, s, off);
        if (lane == 0) {
            const int blk = b >> 5;
            g_drive[blk * (TT * CPB) + t * CPB + (b & 31)] = s;
            red_release_add(&g_ctr[blk * NCHUNK + chunk], 1u);
        }
    }
}

// ---------------------------------------------------------------------------
// consumer: LIF scan for 32 chains; tracks producer chunk-by-chunk.
// Counter c is reset by tid 0 AFTER the __syncthreads that proves every
// thread of this (sole waiting) block observed it full -> race-free,
// leaves all counters zero for the next graph replay.
// ---------------------------------------------------------------------------
__device__ void scan_part(int blk, float* __restrict__ out) {
    __shared__ float sd[2][CHUNK * CPB];   // drive staging [t][chain]
    __shared__ float sv[CPB * PAD];        // v staging [chain][t]

    const int tid = threadIdx.x;           // 0..255
    const int b0  = blk * CPB;
    const float4* __restrict__ gsrc =
        (const float4*)(g_drive + (size_t)blk * TT * CPB);
    const int F4C = CHUNK * CPB / 4;       // 400 float4 per chunk
    const unsigned FULL = (unsigned)(CHUNK * CPB);

    // wait for + stage chunk 0 (each thread acquires -> its cp.asyncs are ordered)
    while (ld_acquire(&g_ctr[blk * NCHUNK + 0]) < FULL) __nanosleep(64);
#pragma unroll
    for (int k = 0; k < 2; k++) {
        int idx = tid + 256 * k;
        if (idx < F4C) cp_async16(&((float4*)sd[0])[idx], &gsrc[idx]);
    }
    cp_async_commit();

    float v = 0.0f;
    bool  p = false;

    for (int c = 0; c < NCHUNK; c++) {
        if (c + 1 < NCHUNK) {
            while (ld_acquire(&g_ctr[blk * NCHUNK + c + 1]) < FULL) __nanosleep(64);
            const float4* src = gsrc + (c + 1) * F4C;
            float4* dst = (float4*)sd[(c + 1) & 1];
#pragma unroll
            for (int k = 0; k < 2; k++) {
                int idx = tid + 256 * k;
                if (idx < F4C) cp_async16(&dst[idx], &src[idx]);
            }
            cp_async_commit();
            cp_async_wait<1>();   // chunk c's group complete
        } else {
            cp_async_wait<0>();
        }
        __syncthreads();          // all threads passed waits for chunks c and c+1

        if (tid == 0) st_relaxed(&g_ctr[blk * NCHUNK + c], 0u);  // replay-safe reset

        if (tid < CPB) {
            const float* __restrict__ d = sd[c & 1];
#pragma unroll
            for (int i = 0; i < CHUNK; i++) {
                float dd = d[i * CPB + tid];        // off-chain LDS
                float w1 = dd - VTH_C;              // off-chain
                v = fmaf(ALPHA_C, v, p ? w1 : dd);  // FSEL + FFMA on chain
                p = (v > VTH_C);                    // FSETP on chain
                sv[tid * PAD + i] = v;              // z recomputed by writers
            }
        }
        __syncthreads();

        // coalesced writeout, all 256 threads; z recomputed from v
        const int tbase = c * CHUNK;
        float* __restrict__ vo = out + (size_t)b0 * TT + tbase;
        float* __restrict__ zo = vo + (size_t)BB * TT;
#pragma unroll
        for (int k = 0; k < 7; k++) {
            int idx = tid + 256 * k;        // 0..1599
            if (idx < CHUNK * CPB) {
                int bb = idx / CHUNK;
                int ii = idx - bb * CHUNK;
                float vv = sv[bb * PAD + ii];
                vo[(size_t)bb * TT + ii] = vv;
                zo[(size_t)bb * TT + ii] = (vv > VTH_C) ? 1.0f : 0.0f;
            }
        }
        // next iteration's __syncthreads orders writeout before sv reuse
    }
}

// ---------------------------------------------------------------------------
// fused kernel: blocks [0,SCB) consume, blocks [SCB, TOTAL) produce
// ---------------------------------------------------------------------------
__global__ void __launch_bounds__(256, 4) lif_fused_kernel(
    const float* __restrict__ x, const float* __restrict__ w,
    float* __restrict__ out) {
    if (blockIdx.x < SCB) {
        scan_part(blockIdx.x, out);
    } else {
        gemv_part(x, w);
    }
}

extern "C" void kernel_launch(void* const* d_in, const int* in_sizes, int n_in,
                              void* d_out, int out_size) {
    const float* x = (const float*)d_in[0];   // [B, T, N] f32
    const float* w = (const float*)d_in[1];   // [N] f32
    float* out = (float*)d_out;               // [2, B, T] f32 (v then z)

    lif_fused_kernel<<<TOTAL_BLOCKS, 256>>>(x, w, out);
}

// round 7
// speedup vs baseline: 1.4041x; 1.4041x over previous
#include <cuda_runtime.h>

#define BB 128
#define TT 1000
#define NN 1024
#define ALPHA_C 0.995f
#define VTH_C 2.0f

#define SCB 4                 // scan blocks
#define CPB (BB / SCB)        // chains per scan block = 32
#define CHUNK 50              // timesteps per chunk
#define NCHUNK (TT / CHUNK)   // 20
#define PAD (CHUNK + 1)       // conflict-free staging stride
#define GEMV_BLOCKS 440
#define TOTAL_BLOCKS (GEMV_BLOCKS + SCB)   // 444 = 3/SM * 148 SM, one wave
#define ROWS_PER_CHUNK (BB * CHUNK)        // 6400
#define GRP 4                               // rows per producer step

// drive scratch, block-major: [SCB][TT][CPB]
__device__ float g_drive[SCB * TT * CPB];
// produced-count per (scan block, chunk); zero at load, re-zeroed by consumer
__device__ unsigned g_ctr[SCB * NCHUNK];

// ---------------------------------------------------------------------------
// sync / copy helpers
// ---------------------------------------------------------------------------
__device__ __forceinline__ void red_release_add(unsigned* p, unsigned v) {
    asm volatile("red.release.gpu.global.add.u32 [%0], %1;"
                 :: "l"(p), "r"(v) : "memory");
}
__device__ __forceinline__ unsigned ld_acquire(const unsigned* p) {
    unsigned v;
    asm volatile("ld.acquire.gpu.global.u32 %0, [%1];"
                 : "=r"(v) : "l"(p) : "memory");
    return v;
}
__device__ __forceinline__ void st_relaxed(unsigned* p, unsigned v) {
    asm volatile("st.relaxed.gpu.global.u32 [%0], %1;"
                 :: "l"(p), "r"(v) : "memory");
}
__device__ __forceinline__ void cp_async16(void* smem_dst, const void* gmem_src) {
    unsigned saddr = (unsigned)__cvta_generic_to_shared(smem_dst);
    asm volatile("cp.async.ca.shared.global [%0], [%1], 16;\n"
                 :: "r"(saddr), "l"(gmem_src) : "memory");
}
__device__ __forceinline__ void cp_async_commit() {
    asm volatile("cp.async.commit_group;\n" ::: "memory");
}
template <int N>
__device__ __forceinline__ void cp_async_wait() {
    asm volatile("cp.async.wait_group %0;\n" :: "n"(N) : "memory");
}

// ---------------------------------------------------------------------------
// producer: drive[b,t] = dot(x[b,t,:], w), warp per row, 4 rows per step.
// Chunk-ordered globally (pacing); one release-atomic per 4-row group.
// ---------------------------------------------------------------------------
__device__ void gemv_part(const float* __restrict__ x, const float* __restrict__ w) {
    const int lane  = threadIdx.x & 31;
    const int warp  = ((blockIdx.x - SCB) * blockDim.x + threadIdx.x) >> 5;
    const int nwarp = (GEMV_BLOCKS * 256) >> 5;     // 3520

    const float4* __restrict__ w4 = (const float4*)w;
    float4 wr[8];
#pragma unroll
    for (int k = 0; k < 8; k++) wr[k] = w4[lane + 32 * k];

    const int G = (BB * TT) / GRP;                   // 32000 groups
    for (int g = warp; g < G; g += nwarp) {
        const int q0    = g * GRP;
        const int chunk = q0 / ROWS_PER_CHUNK;       // same for whole group
        const int rem0  = q0 - chunk * ROWS_PER_CHUNK;
        const int blk   = rem0 / (CPB * CHUNK);      // same for whole group

#pragma unroll
        for (int r = 0; r < GRP; r++) {
            const int rem = rem0 + r;
            const int b   = rem / CHUNK;
            const int t   = chunk * CHUNK + (rem - b * CHUNK);

            const float4* __restrict__ x4 =
                (const float4*)(x + ((size_t)b * TT + t) * NN);
            float s = 0.0f;
#pragma unroll
            for (int k = 0; k < 8; k++) {            // MLP = 8 (needs ~80 regs)
                float4 xv = x4[lane + 32 * k];
                s += xv.x * wr[k].x;
                s += xv.y * wr[k].y;
                s += xv.z * wr[k].z;
                s += xv.w * wr[k].w;
            }
#pragma unroll
            for (int off = 16; off > 0; off >>= 1)
                s += __shfl_xor_sync(0xffffffffu, s, off);
            if (lane == 0)
                g_drive[blk * (TT * CPB) + t * CPB + (b & 31)] = s;
        }
        if (lane == 0)
            red_release_add(&g_ctr[blk * NCHUNK + chunk], GRP);
    }
}

// ---------------------------------------------------------------------------
// consumer: LIF scan for 32 chains; tracks producer chunk-by-chunk.
// ---------------------------------------------------------------------------
__device__ void scan_part(int blk, float* __restrict__ out) {
    __shared__ float sd[2][CHUNK * CPB];   // drive staging [t][chain]
    __shared__ float sv[CPB * PAD];        // v staging [chain][t]

    const int tid = threadIdx.x;           // 0..255
    const int b0  = blk * CPB;
    const float4* __restrict__ gsrc =
        (const float4*)(g_drive + (size_t)blk * TT * CPB);
    const int F4C = CHUNK * CPB / 4;       // 400 float4 per chunk
    const unsigned FULL = (unsigned)(CHUNK * CPB);

    while (ld_acquire(&g_ctr[blk * NCHUNK + 0]) < FULL) __nanosleep(64);
#pragma unroll
    for (int k = 0; k < 2; k++) {
        int idx = tid + 256 * k;
        if (idx < F4C) cp_async16(&((float4*)sd[0])[idx], &gsrc[idx]);
    }
    cp_async_commit();

    float v = 0.0f;
    bool  p = false;

    for (int c = 0; c < NCHUNK; c++) {
        if (c + 1 < NCHUNK) {
            while (ld_acquire(&g_ctr[blk * NCHUNK + c + 1]) < FULL) __nanosleep(64);
            const float4* src = gsrc + (c + 1) * F4C;
            float4* dst = (float4*)sd[(c + 1) & 1];
#pragma unroll
            for (int k = 0; k < 2; k++) {
                int idx = tid + 256 * k;
                if (idx < F4C) cp_async16(&dst[idx], &src[idx]);
            }
            cp_async_commit();
            cp_async_wait<1>();   // chunk c's group complete
        } else {
            cp_async_wait<0>();
        }
        __syncthreads();          // all threads passed waits for chunks c, c+1

        if (tid == 0) st_relaxed(&g_ctr[blk * NCHUNK + c], 0u);  // replay-safe

        if (tid < CPB) {
            const float* __restrict__ d = sd[c & 1];
#pragma unroll
            for (int i = 0; i < CHUNK; i++) {
                float dd = d[i * CPB + tid];        // off-chain LDS
                float w1 = dd - VTH_C;              // off-chain
                v = fmaf(ALPHA_C, v, p ? w1 : dd);  // FSEL + FFMA on chain
                p = (v > VTH_C);                    // FSETP on chain
                sv[tid * PAD + i] = v;              // z recomputed by writers
            }
        }
        __syncthreads();

        const int tbase = c * CHUNK;
        float* __restrict__ vo = out + (size_t)b0 * TT + tbase;
        float* __restrict__ zo = vo + (size_t)BB * TT;
#pragma unroll
        for (int k = 0; k < 7; k++) {
            int idx = tid + 256 * k;        // 0..1599
            if (idx < CHUNK * CPB) {
                int bb = idx / CHUNK;
                int ii = idx - bb * CHUNK;
                float vv = sv[bb * PAD + ii];
                vo[(size_t)bb * TT + ii] = vv;
                zo[(size_t)bb * TT + ii] = (vv > VTH_C) ? 1.0f : 0.0f;
            }
        }
    }
}

// ---------------------------------------------------------------------------
// fused kernel: blocks [0,SCB) consume, blocks [SCB, TOTAL) produce
// 3 blocks/SM (85-reg budget -> full MLP in the gemv loop), one wave.
// ---------------------------------------------------------------------------
__global__ void __launch_bounds__(256, 3) lif_fused_kernel(
    const float* __restrict__ x, const float* __restrict__ w,
    float* __restrict__ out) {
    if (blockIdx.x < SCB) {
        scan_part(blockIdx.x, out);
    } else {
        gemv_part(x, w);
    }
}

extern "C" void kernel_launch(void* const* d_in, const int* in_sizes, int n_in,
                              void* d_out, int out_size) {
    const float* x = (const float*)d_in[0];   // [B, T, N] f32
    const float* w = (const float*)d_in[1];   // [N] f32
    float* out = (float*)d_out;               // [2, B, T] f32 (v then z)

    lif_fused_kernel<<<TOTAL_BLOCKS, 256>>>(x, w, out);
}